// round 4
// baseline (speedup 1.0000x reference)
#include <cuda_runtime.h>
#include <cuda_fp16.h>
#include <mma.h>

using namespace nvcuda;

#define Bc 4
#define Sc 1024
#define Ec 512
#define Hc 8
#define Dc 64
#define BHc 32

// ---- scratch (device globals; no runtime allocation allowed) ----
__device__ __half g_Qh[BHc * Sc * Dc];            // 4 MB  [bh][s][d]  (prescaled by 1/8)
__device__ __half g_Kh[BHc * Sc * Dc];            // 4 MB  [bh][t][d]
__device__ __half g_Ch[BHc * Sc * Dc];            // 4 MB  [bh][t][d]
__device__ __half g_Th[Bc * Sc * Ec];             // 4 MB  [b][t][e]
__device__ __half g_W[(size_t)BHc * Sc * Sc];     // 64 MB [bh][i][t]  (normalized weights)

__device__ __forceinline__ float fast_tanh(float x) {
    float y;
    asm("tanh.approx.f32 %0, %1;" : "=f"(y) : "f"(x));
    return y;
}

// ---- K0: convert + head-split to fp16 (Q prescaled by 1/8) ----
__global__ void convert_kernel(const float* __restrict__ src,
                               const float* __restrict__ tgt) {
    int idx = blockIdx.x * blockDim.x + threadIdx.x;
    if (idx >= Bc * Sc * Ec) return;
    int e = idx % Ec;
    int s = (idx / Ec) % Sc;
    int b = idx / (Ec * Sc);
    int h = e / Dc, d = e % Dc;
    float sv = src[idx], tv = tgt[idx];
    int qidx = ((b * Hc + h) * Sc + s) * Dc + d;
    g_Qh[qidx] = __float2half(sv * 0.125f);
    g_Kh[qidx] = __float2half(tv);
    g_Th[idx]  = __float2half(tv);
}

// ---- K1: sequential recurrence with register prefetch (MLP=8) ----
__global__ void recurrence_kernel(const float* __restrict__ tgt,
                                  const float* __restrict__ enc) {
    int bh = blockIdx.x;
    int d = threadIdx.x;
    int b = bh / Hc, h = bh % Hc;
    float pe = enc[h * Dc + d];
    const float* kp = tgt + (size_t)b * Sc * Ec + h * Dc + d;  // stride Ec per t
    __half* cp = g_Ch + (size_t)bh * Sc * Dc + d;              // stride Dc per t
    float c = kp[0];
    float kv[8];
#pragma unroll
    for (int j = 0; j < 8; j++) kv[j] = kp[(size_t)j * Ec];
    for (int t = 0; t < Sc; t += 8) {
#pragma unroll
        for (int j = 0; j < 8; j++) {
            float kt = kv[j];
            int tp = t + 8 + j;
            if (tp < Sc) kv[j] = kp[(size_t)tp * Ec];
            float ct = fast_tanh(c * pe);
            cp[(size_t)(t + j) * Dc] = __float2half(ct);
            c = kt * ct;
        }
    }
}

// ---- K2: fused dual-GEMM + dual-softmax -> W (per 64-row strip) ----
// grid (Sc/64, 1, BHc), 256 threads (8 warps).
// smem: expg[64][1024] h (gram logits -> gram probs -> P), Qs 64x64, KCs 64x64,
//       stg 64x64, rowred[64] f32.
__global__ void fused_softmax_gemm(const float* __restrict__ ap,
                                   const float* __restrict__ bp,
                                   const float* __restrict__ gp) {
    extern __shared__ char smraw[];
    __half* expg = (__half*)smraw;            // 64*1024
    __half* Qs   = expg + 64 * 1024;          // 64*64
    __half* KCs  = Qs + 64 * 64;              // 64*64
    __half* stg  = KCs + 64 * 64;             // 64*64
    float* rowred = (float*)(stg + 64 * 64);  // 64 floats

    int bh = blockIdx.z;
    int i0 = blockIdx.x * 64;
    int tid = threadIdx.x;
    int warp = tid >> 5;
    int mi = warp & 3;   // 16-row strip within 64
    int nh = warp >> 1 & 0;  // placeholder (unused)
    (void)nh;
    int nhh = warp >> 2; // 0/1 : 32-col half of 64-col chunk

    float alpha = ap[0], beta = bp[0], ginv = 1.0f / gp[0];
    float sc = alpha * 0.08f * ginv;   // semantic scale (x8 from Q prescale, /100, /gamma)

    // load Q strip (64x64)
    {
        const int4* qsrc = (const int4*)(g_Qh + (size_t)bh * Sc * Dc + (size_t)i0 * Dc);
        int4* qd = (int4*)Qs;
        qd[tid] = qsrc[tid];
        qd[tid + 256] = qsrc[tid + 256];
    }

    // ---- pass A: grammar logits = Q' . C  -> expg (as logits) ----
    for (int t0 = 0; t0 < Sc; t0 += 64) {
        __syncthreads();
        const int4* csrc = (const int4*)(g_Ch + (size_t)bh * Sc * Dc + (size_t)t0 * Dc);
        int4* cd = (int4*)KCs;
        cd[tid] = csrc[tid];
        cd[tid + 256] = csrc[tid + 256];
        __syncthreads();
        wmma::fragment<wmma::accumulator, 16, 16, 16, __half> cg[2];
#pragma unroll
        for (int j = 0; j < 2; j++) wmma::fill_fragment(cg[j], __float2half(0.0f));
#pragma unroll
        for (int kk = 0; kk < 4; kk++) {
            wmma::fragment<wmma::matrix_a, 16, 16, 16, __half, wmma::row_major> a;
            wmma::load_matrix_sync(a, Qs + mi * 16 * 64 + kk * 16, 64);
#pragma unroll
            for (int j = 0; j < 2; j++) {
                wmma::fragment<wmma::matrix_b, 16, 16, 16, __half, wmma::col_major> bfr;
                wmma::load_matrix_sync(bfr, KCs + (nhh * 32 + j * 16) * 64 + kk * 16, 64);
                wmma::mma_sync(cg[j], a, bfr, cg[j]);
            }
        }
#pragma unroll
        for (int j = 0; j < 2; j++)
            wmma::store_matrix_sync(expg + mi * 16 * 1024 + t0 + nhh * 32 + j * 16,
                                    cg[j], 1024, wmma::mem_row_major);
    }
    __syncthreads();

    // ---- in-place exp + grammar row sums ----
    {
        int r = tid >> 2;
        int c0 = (tid & 3) * 256;
        __half* row = expg + r * 1024 + c0;
        float s = 0.0f;
        for (int c = 0; c < 256; c += 2) {
            float2 f = __half22float2(*(half2*)(row + c));
            float e0 = exp2f(f.x * 1.44269504f);
            float e1 = exp2f(f.y * 1.44269504f);
            s += e0 + e1;
            *(half2*)(row + c) = __floats2half2_rn(e0, e1);
        }
        s += __shfl_xor_sync(0xffffffffu, s, 1);
        s += __shfl_xor_sync(0xffffffffu, s, 2);
        if ((tid & 3) == 0) rowred[r] = s;
    }
    __syncthreads();

    int r = tid >> 2;
    float wgt = beta * ginv / rowred[r];
    float psum = 0.0f;

    // ---- pass B: semantic = Q' . K ; combine; P = exp(l) in place ----
    for (int t0 = 0; t0 < Sc; t0 += 64) {
        __syncthreads();
        const int4* ksrc = (const int4*)(g_Kh + (size_t)bh * Sc * Dc + (size_t)t0 * Dc);
        int4* kd = (int4*)KCs;
        kd[tid] = ksrc[tid];
        kd[tid + 256] = ksrc[tid + 256];
        __syncthreads();
        wmma::fragment<wmma::accumulator, 16, 16, 16, __half> cs[2];
#pragma unroll
        for (int j = 0; j < 2; j++) wmma::fill_fragment(cs[j], __float2half(0.0f));
#pragma unroll
        for (int kk = 0; kk < 4; kk++) {
            wmma::fragment<wmma::matrix_a, 16, 16, 16, __half, wmma::row_major> a;
            wmma::load_matrix_sync(a, Qs + mi * 16 * 64 + kk * 16, 64);
#pragma unroll
            for (int j = 0; j < 2; j++) {
                wmma::fragment<wmma::matrix_b, 16, 16, 16, __half, wmma::col_major> bfr;
                wmma::load_matrix_sync(bfr, KCs + (nhh * 32 + j * 16) * 64 + kk * 16, 64);
                wmma::mma_sync(cs[j], a, bfr, cs[j]);
            }
        }
#pragma unroll
        for (int j = 0; j < 2; j++)
            wmma::store_matrix_sync(stg + mi * 16 * 64 + nhh * 32 + j * 16,
                                    cs[j], 64, wmma::mem_row_major);
        __syncthreads();
        // elementwise combine (4 threads per row, 16 cols each)
        {
            int c0 = (tid & 3) * 16;
            __half* sr = stg + r * 64 + c0;
            __half* er = expg + r * 1024 + t0 + c0;
#pragma unroll
            for (int c = 0; c < 16; c += 2) {
                float2 sv = __half22float2(*(half2*)(sr + c));
                float2 ev = __half22float2(*(half2*)(er + c));
                float p0 = exp2f((sv.x * sc + wgt * ev.x) * 1.44269504f);
                float p1 = exp2f((sv.y * sc + wgt * ev.y) * 1.44269504f);
                psum += p0 + p1;
                *(half2*)(er + c) = __floats2half2_rn(p0, p1);
            }
        }
    }
    // reduce psum over the 4 threads owning each row
    psum += __shfl_xor_sync(0xffffffffu, psum, 1);
    psum += __shfl_xor_sync(0xffffffffu, psum, 2);
    if ((tid & 3) == 0) rowred[r] = 1.0f / psum;
    __syncthreads();

    // ---- normalize (fp32) + write W ----
    __half* wbase = g_W + (size_t)bh * Sc * Sc + (size_t)i0 * Sc;
    for (int rr = 0; rr < 64; rr++) {
        float inv = rowred[rr];
        half2* srcp = (half2*)(expg + rr * 1024);
        half2* dstp = (half2*)(wbase + (size_t)rr * Sc);
#pragma unroll
        for (int l = 0; l < 2; l++) {
            int o = tid + l * 256;
            float2 f = __half22float2(srcp[o]);
            dstp[o] = __floats2half2_rn(f.x * inv, f.y * inv);
        }
    }
}

// ---- K4: out[bh,t,e] = sum_s W[bh,s,t] * Th[b,s,e]   (W^T @ target) ----
__global__ void out_gemm(float* __restrict__ out) {
    int bh = blockIdx.z;
    int b = bh / Hc;
    int t0 = blockIdx.x * 128;
    int e0 = blockIdx.y * 64;
    __shared__ __half Ws[64 * 128];  // [s][t]
    __shared__ __half Ts[64 * 64];   // [s][e]
    int tid = threadIdx.x;
    int warp = tid >> 5;
    int r0 = warp * 16;  // t-strip within tile

    wmma::fragment<wmma::accumulator, 16, 16, 16, float> acc[4];
#pragma unroll
    for (int n = 0; n < 4; n++) wmma::fill_fragment(acc[n], 0.0f);

    for (int s0 = 0; s0 < Sc; s0 += 64) {
        const __half* wsrc = g_W + (size_t)bh * Sc * Sc + (size_t)s0 * Sc + t0;
#pragma unroll
        for (int l = 0; l < 4; l++) {
            int o = tid + l * 256;
            int rr = o >> 4, c = o & 15;
            ((int4*)Ws)[rr * 16 + c] = ((const int4*)(wsrc + (size_t)rr * Sc))[c];
        }
        const __half* tsrc = g_Th + (size_t)b * Sc * Ec + (size_t)s0 * Ec + e0;
#pragma unroll
        for (int l = 0; l < 2; l++) {
            int o = tid + l * 256;
            int rr = o >> 3, c = o & 7;
            ((int4*)Ts)[rr * 8 + c] = ((const int4*)(tsrc + (size_t)rr * Ec))[c];
        }
        __syncthreads();
#pragma unroll
        for (int kk = 0; kk < 4; kk++) {
            wmma::fragment<wmma::matrix_a, 16, 16, 16, __half, wmma::col_major> a;
            wmma::load_matrix_sync(a, Ws + kk * 16 * 128 + r0, 128);
#pragma unroll
            for (int n = 0; n < 4; n++) {
                wmma::fragment<wmma::matrix_b, 16, 16, 16, __half, wmma::row_major> bf;
                wmma::load_matrix_sync(bf, Ts + kk * 16 * 64 + n * 16, 64);
                wmma::mma_sync(acc[n], a, bf, acc[n]);
            }
        }
        __syncthreads();
    }
    float* obase = out + (size_t)bh * Sc * Ec + (size_t)(t0 + r0) * Ec + e0;
#pragma unroll
    for (int n = 0; n < 4; n++)
        wmma::store_matrix_sync(obase + n * 16, acc[n], Ec, wmma::mem_row_major);
}

extern "C" void kernel_launch(void* const* d_in, const int* in_sizes, int n_in,
                              void* d_out, int out_size) {
    (void)in_sizes; (void)n_in; (void)out_size;
    const float* source = (const float*)d_in[0];
    const float* target = (const float*)d_in[1];
    const float* encoder = (const float*)d_in[2];
    const float* alpha = (const float*)d_in[3];
    const float* beta = (const float*)d_in[4];
    const float* gamma = (const float*)d_in[5];
    float* out = (float*)d_out;

    const int FUSED_SMEM = 64 * 1024 * 2 + 3 * 64 * 64 * 2 + 64 * 4;  // 155,904 B
    static int attr_done = 0;
    if (!attr_done) {
        cudaFuncSetAttribute(fused_softmax_gemm,
                             cudaFuncAttributeMaxDynamicSharedMemorySize, FUSED_SMEM);
        attr_done = 1;
    }

    int nconv = Bc * Sc * Ec;
    convert_kernel<<<(nconv + 255) / 256, 256>>>(source, target);
    recurrence_kernel<<<BHc, Dc>>>(target, encoder);
    fused_softmax_gemm<<<dim3(Sc / 64, 1, BHc), 256, FUSED_SMEM>>>(alpha, beta, gamma);
    out_gemm<<<dim3(Sc / 128, Ec / 64, BHc), 256>>>(out);
}

// round 7
// speedup vs baseline: 3.9848x; 3.9848x over previous
#include <cuda_runtime.h>
#include <cuda_fp16.h>
#include <mma.h>
#include <cstdint>

using namespace nvcuda;

#define Bc 4
#define Sc 1024
#define Ec 512
#define Hc 8
#define Dc 64
#define BHc 32
#define LOG2E 1.4426950408889634f

// ---- scratch (device globals; no runtime allocation allowed) ----
__device__ __half g_Qh[BHc * Sc * Dc];            // 4 MB  [bh][s][d]  (prescaled by log2e/8)
__device__ __half g_Kh[BHc * Sc * Dc];            // 4 MB  [bh][t][d]
__device__ __half g_Ch[BHc * Sc * Dc];            // 4 MB  [bh][t][d]
__device__ __half g_Th[Bc * Sc * Ec];             // 4 MB  [b][t][e]
__device__ __half g_WT[(size_t)BHc * Sc * Sc];    // 64 MB [bh][t][s]  W TRANSPOSED

__device__ __forceinline__ float fast_tanh(float x) {
    float y;
    asm("tanh.approx.f32 %0, %1;" : "=f"(y) : "f"(x));
    return y;
}

__device__ __forceinline__ half2 h2ex2(half2 x) {
    half2 y;
    asm("ex2.approx.f16x2 %0, %1;"
        : "=r"(*reinterpret_cast<unsigned int*>(&y))
        : "r"(*reinterpret_cast<unsigned int*>(&x)));
    return y;
}

// ---- K0: convert + head-split to fp16 (Q prescaled by log2e/8) ----
__global__ void convert_kernel(const float* __restrict__ src,
                               const float* __restrict__ tgt) {
    int idx = blockIdx.x * blockDim.x + threadIdx.x;
    if (idx >= Bc * Sc * Ec) return;
    int e = idx % Ec;
    int s = (idx / Ec) % Sc;
    int b = idx / (Ec * Sc);
    int h = e / Dc, d = e % Dc;
    float sv = src[idx], tv = tgt[idx];
    int qidx = ((b * Hc + h) * Sc + s) * Dc + d;
    g_Qh[qidx] = __float2half(sv * (0.125f * LOG2E));
    g_Kh[qidx] = __float2half(tv);
    g_Th[idx]  = __float2half(tv);
}

// ---- K1: sequential recurrence with register prefetch ----
__global__ void recurrence_kernel(const float* __restrict__ tgt,
                                  const float* __restrict__ enc) {
    int bh = blockIdx.x;
    int d = threadIdx.x;
    int b = bh / Hc, h = bh % Hc;
    float pe = enc[h * Dc + d];
    const float* kp = tgt + (size_t)b * Sc * Ec + h * Dc + d;
    __half* cp = g_Ch + (size_t)bh * Sc * Dc + d;
    float c = kp[0];
    float kv[8];
#pragma unroll
    for (int j = 0; j < 8; j++) kv[j] = kp[(size_t)j * Ec];
    for (int t = 0; t < Sc; t += 8) {
#pragma unroll
        for (int j = 0; j < 8; j++) {
            float kt = kv[j];
            int tp = t + 8 + j;
            if (tp < Sc) kv[j] = kp[(size_t)tp * Ec];
            float ct = fast_tanh(c * pe);
            cp[(size_t)(t + j) * Dc] = __float2half(ct);
            c = kt * ct;
        }
    }
}

// ---- K2: fused dual-GEMM + dual-softmax -> W^T (64-row strip, 512 threads) ----
// Logits come out of the GEMM already scaled by log2e (Q prescale), so exp is a
// bare ex2.approx.f16x2. Grammar exp is fused into the per-chunk epilogue.
// smem: expg[64][1024] h, Qs[64][72], KCs[64][72], stg[64][72], rowred[64] f32
__global__ void fused_softmax_gemm(const float* __restrict__ ap,
                                   const float* __restrict__ bp,
                                   const float* __restrict__ gp) {
    extern __shared__ char smraw[];
    __half* expg = (__half*)smraw;              // 64*1024
    __half* Qs   = expg + 64 * 1024;            // 64*72 (padded)
    __half* KCs  = Qs + 64 * 72;
    __half* stg  = KCs + 64 * 72;
    float* rowred = (float*)(stg + 64 * 72);

    int bh = blockIdx.y;
    int i0 = blockIdx.x * 64;
    int tid = threadIdx.x;
    int warp = tid >> 5;
    int mi = warp >> 2;      // 0..3 : 16-row strip
    int ni = warp & 3;       // 0..3 : 16-col strip within 64-chunk
    int r  = tid >> 3;       // 0..63: row owned in epilogue
    int c8 = (tid & 7) * 8;  // 8 cols per thread per chunk

    float alpha = ap[0], beta = bp[0], ginv = 1.0f / gp[0];
    float sc2 = 0.08f * alpha * ginv;  // semantic scale on GEMM output

    // load Q strip (64x64 -> padded 64x72)
    {
        const int4* qs = (const int4*)(g_Qh + ((size_t)bh << 16) + (size_t)i0 * Dc);
        ((int4*)Qs)[(tid >> 3) * 9 + (tid & 7)] = qs[tid];
    }

    // ---- pass A: gl = (Q.C)*log2e/8 -> ev=2^gl -> expg; Zg row sums ----
    float zsum = 0.0f;
    for (int t0 = 0; t0 < Sc; t0 += 64) {
        __syncthreads();
        const int4* cs = (const int4*)(g_Ch + ((size_t)bh << 16) + (size_t)t0 * Dc);
        ((int4*)KCs)[(tid >> 3) * 9 + (tid & 7)] = cs[tid];
        __syncthreads();
        wmma::fragment<wmma::accumulator, 16, 16, 16, __half> acc;
        wmma::fill_fragment(acc, __float2half(0.0f));
#pragma unroll
        for (int kk = 0; kk < 4; kk++) {
            wmma::fragment<wmma::matrix_a, 16, 16, 16, __half, wmma::row_major> a;
            wmma::load_matrix_sync(a, Qs + mi * 16 * 72 + kk * 16, 72);
            wmma::fragment<wmma::matrix_b, 16, 16, 16, __half, wmma::col_major> bf;
            wmma::load_matrix_sync(bf, KCs + ni * 16 * 72 + kk * 16, 72);
            wmma::mma_sync(acc, a, bf, acc);
        }
        wmma::store_matrix_sync(stg + mi * 16 * 72 + ni * 16, acc, 72, wmma::mem_row_major);
        __syncthreads();
        // exp epilogue: ev = 2^gl, accumulate row sum, store to expg
        int4 v = *(int4*)(stg + r * 72 + c8);
        half2* hv = (half2*)&v;
        int4 o;
        half2* ho = (half2*)&o;
#pragma unroll
        for (int j = 0; j < 4; j++) {
            half2 e = h2ex2(hv[j]);
            float2 f = __half22float2(e);
            zsum += f.x + f.y;
            ho[j] = e;
        }
        *(int4*)(expg + r * 1024 + t0 + c8) = o;
    }
    zsum += __shfl_xor_sync(0xffffffffu, zsum, 1);
    zsum += __shfl_xor_sync(0xffffffffu, zsum, 2);
    zsum += __shfl_xor_sync(0xffffffffu, zsum, 4);
    if ((tid & 7) == 0) rowred[r] = zsum;
    __syncthreads();

    float wgt2 = LOG2E * beta * ginv / rowred[r];
    half2 sch = __floats2half2_rn(sc2, sc2);
    half2 wgh = __floats2half2_rn(wgt2, wgt2);
    float psum = 0.0f;

    // ---- pass B: sl = (Q.K)*log2e/8; P = 2^(sl*sc2 + ev*wgt2) -> expg ----
    for (int t0 = 0; t0 < Sc; t0 += 64) {
        __syncthreads();
        const int4* ks = (const int4*)(g_Kh + ((size_t)bh << 16) + (size_t)t0 * Dc);
        ((int4*)KCs)[(tid >> 3) * 9 + (tid & 7)] = ks[tid];
        __syncthreads();
        wmma::fragment<wmma::accumulator, 16, 16, 16, __half> acc;
        wmma::fill_fragment(acc, __float2half(0.0f));
#pragma unroll
        for (int kk = 0; kk < 4; kk++) {
            wmma::fragment<wmma::matrix_a, 16, 16, 16, __half, wmma::row_major> a;
            wmma::load_matrix_sync(a, Qs + mi * 16 * 72 + kk * 16, 72);
            wmma::fragment<wmma::matrix_b, 16, 16, 16, __half, wmma::col_major> bf;
            wmma::load_matrix_sync(bf, KCs + ni * 16 * 72 + kk * 16, 72);
            wmma::mma_sync(acc, a, bf, acc);
        }
        wmma::store_matrix_sync(stg + mi * 16 * 72 + ni * 16, acc, 72, wmma::mem_row_major);
        __syncthreads();
        // combine epilogue
        int4 sv = *(int4*)(stg + r * 72 + c8);
        int4 ev = *(int4*)(expg + r * 1024 + t0 + c8);
        half2* hs = (half2*)&sv;
        half2* he = (half2*)&ev;
        int4 o;
        half2* ho = (half2*)&o;
#pragma unroll
        for (int j = 0; j < 4; j++) {
            half2 p = h2ex2(__hfma2(hs[j], sch, __hmul2(he[j], wgh)));
            float2 f = __half22float2(p);
            psum += f.x + f.y;
            ho[j] = p;
        }
        *(int4*)(expg + r * 1024 + t0 + c8) = o;
    }
    psum += __shfl_xor_sync(0xffffffffu, psum, 1);
    psum += __shfl_xor_sync(0xffffffffu, psum, 2);
    psum += __shfl_xor_sync(0xffffffffu, psum, 4);
    if ((tid & 7) == 0) rowred[r] = 1.0f / psum;
    __syncthreads();

    // ---- normalize + TRANSPOSED write: g_WT[bh][t][i0..i0+63] ----
    for (int t = tid; t < Sc; t += 512) {
        half2 arr[32];
#pragma unroll
        for (int p = 0; p < 32; p++) {
            float v0 = __half2float(expg[(2 * p) * 1024 + t]) * rowred[2 * p];
            float v1 = __half2float(expg[(2 * p + 1) * 1024 + t]) * rowred[2 * p + 1];
            arr[p] = __floats2half2_rn(v0, v1);
        }
        int4* dst = (int4*)(g_WT + ((size_t)bh << 20) + (size_t)t * 1024 + i0);
#pragma unroll
        for (int q = 0; q < 8; q++) dst[q] = ((int4*)arr)[q];
    }
}

// ---- K4: out[bh,t,e] = sum_s WT[bh,t,s] * Th[b,s,e]  (plain row-major GEMM) ----
// 128(t) x 128(e) tile, 256 threads (8 warps = 2m x 4n), K-chunks of 64,
// register-prefetch double buffering, padded smem (ldm 72 / 136).
__global__ void __launch_bounds__(256) out_gemm(float* __restrict__ out) {
    __shared__ __half As[128 * 72];
    __shared__ __half Bs[64 * 136];
    int bh = blockIdx.z, b = bh >> 3;
    int t0 = blockIdx.x * 128, e0 = blockIdx.y * 128;
    int tid = threadIdx.x, warp = tid >> 5;
    int mi = warp >> 2;  // 0..1
    int ni = warp & 3;   // 0..3

    const __half* Abase = g_WT + ((size_t)bh << 20) + (size_t)t0 * 1024;
    const __half* Bbase = g_Th + ((size_t)b << 19) + e0;

    wmma::fragment<wmma::accumulator, 16, 16, 16, float> acc[4][2];
#pragma unroll
    for (int m = 0; m < 4; m++)
#pragma unroll
        for (int n = 0; n < 2; n++) wmma::fill_fragment(acc[m][n], 0.0f);

    int4 ar[4], br[4];
#pragma unroll
    for (int l = 0; l < 4; l++) {
        int o = tid + l * 256;
        ar[l] = *(const int4*)(Abase + (size_t)(o >> 3) * 1024 + (o & 7) * 8);
        br[l] = *(const int4*)(Bbase + (size_t)(o >> 4) * 512 + (o & 15) * 8);
    }

    for (int c = 0; c < 16; c++) {
        __syncthreads();
#pragma unroll
        for (int l = 0; l < 4; l++) {
            int o = tid + l * 256;
            ((int4*)As)[(o >> 3) * 9 + (o & 7)] = ar[l];
            ((int4*)Bs)[(o >> 4) * 17 + (o & 15)] = br[l];
        }
        __syncthreads();
        if (c < 15) {
            int s0 = (c + 1) * 64;
#pragma unroll
            for (int l = 0; l < 4; l++) {
                int o = tid + l * 256;
                ar[l] = *(const int4*)(Abase + (size_t)(o >> 3) * 1024 + s0 + (o & 7) * 8);
                br[l] = *(const int4*)(Bbase + (size_t)((o >> 4) + s0) * 512 + (o & 15) * 8);
            }
        }
#pragma unroll
        for (int kk = 0; kk < 4; kk++) {
            wmma::fragment<wmma::matrix_a, 16, 16, 16, __half, wmma::row_major> af[4];
#pragma unroll
            for (int m = 0; m < 4; m++)
                wmma::load_matrix_sync(af[m], As + (mi * 64 + m * 16) * 72 + kk * 16, 72);
#pragma unroll
            for (int n = 0; n < 2; n++) {
                wmma::fragment<wmma::matrix_b, 16, 16, 16, __half, wmma::row_major> bf;
                wmma::load_matrix_sync(bf, Bs + kk * 16 * 136 + ni * 32 + n * 16, 136);
#pragma unroll
                for (int m = 0; m < 4; m++) wmma::mma_sync(acc[m][n], af[m], bf, acc[m][n]);
            }
        }
    }
#pragma unroll
    for (int m = 0; m < 4; m++)
#pragma unroll
        for (int n = 0; n < 2; n++)
            wmma::store_matrix_sync(
                out + ((size_t)bh << 19) + (size_t)(t0 + mi * 64 + m * 16) * 512
                    + e0 + ni * 32 + n * 16,
                acc[m][n], 512, wmma::mem_row_major);
}

extern "C" void kernel_launch(void* const* d_in, const int* in_sizes, int n_in,
                              void* d_out, int out_size) {
    (void)in_sizes; (void)n_in; (void)out_size;
    const float* source = (const float*)d_in[0];
    const float* target = (const float*)d_in[1];
    const float* encoder = (const float*)d_in[2];
    const float* alpha = (const float*)d_in[3];
    const float* beta = (const float*)d_in[4];
    const float* gamma = (const float*)d_in[5];
    float* out = (float*)d_out;

    const int FUSED_SMEM = 64 * 1024 * 2 + 3 * 64 * 72 * 2 + 64 * 4;  // 158,848 B
    static int attr_done = 0;
    if (!attr_done) {
        cudaFuncSetAttribute(fused_softmax_gemm,
                             cudaFuncAttributeMaxDynamicSharedMemorySize, FUSED_SMEM);
        attr_done = 1;
    }

    int nconv = Bc * Sc * Ec;
    convert_kernel<<<(nconv + 255) / 256, 256>>>(source, target);
    recurrence_kernel<<<BHc, Dc>>>(target, encoder);
    fused_softmax_gemm<<<dim3(Sc / 64, BHc), 512, FUSED_SMEM>>>(alpha, beta, gamma);
    out_gemm<<<dim3(Sc / 128, Ec / 128, BHc), 256>>>(out);
}